// round 5
// baseline (speedup 1.0000x reference)
#include <cuda_runtime.h>

// Fixed problem shapes (SpanRepresentation_32487132627590)
#define BATCH   4
#define SLEN    2048
#define DIM     768
#define DIM4    (DIM / 4)               // 192 float4 lanes
#define NSPAN   4096
#define NROWS   (BATCH * NSPAN)         // 16384 output rows
#define CHUNK   16
#define NCHUNK  (SLEN / CHUNK)          // 128
#define NCBLK   (BATCH * NCHUNK)        // 512 scan blocks
#define OUTW    2364
#define OFF_MEAN 0
#define OFF_XS0  768
#define OFF_P0   1536
#define OFF_XS1  1556
#define OFF_P1   2324
#define OFF_W    2344

// exclusive prefix sums cs[b, s, d], s in [0, SLEN]  (~25.2 MB)
__device__ float g_cs[(size_t)BATCH * (SLEN + 1) * DIM];
// decoupled-lookback state
__device__ float g_aggr[(size_t)NCBLK * DIM];
__device__ float g_incl[(size_t)NCBLK * DIM];
__device__ int   g_flag[NCBLK];

static __device__ __forceinline__ float4 f4add(float4 a, float4 b) {
    a.x += b.x; a.y += b.y; a.z += b.z; a.w += b.w; return a;
}
static __device__ __forceinline__ int ld_acq(const int* p) {
    int v; asm volatile("ld.global.acquire.gpu.b32 %0, [%1];" : "=r"(v) : "l"(p) : "memory"); return v;
}
static __device__ __forceinline__ void st_rel(int* p, int v) {
    asm volatile("st.global.release.gpu.b32 [%0], %1;" :: "l"(p), "r"(v) : "memory");
}

// ---------------------------------------------------------------------------
// Kernel 0: reset lookback flags (must run each launch for graph replay)
// ---------------------------------------------------------------------------
__global__ void zero_flags_kernel() { g_flag[threadIdx.x] = 0; }

// ---------------------------------------------------------------------------
// Kernel 1: single-pass scan with decoupled lookback.  grid=512, block=192
// ---------------------------------------------------------------------------
__global__ __launch_bounds__(DIM4)
void scan_kernel(const float* __restrict__ x) {
    const int t  = threadIdx.x;
    const int bc = blockIdx.x;
    const int b  = bc / NCHUNK;
    const int c  = bc % NCHUNK;

    // chunks are contiguous in memory: base = bc*CHUNK*DIM
    const float4* p = (const float4*)(x + (size_t)bc * CHUNK * DIM) + t;

    // local aggregate (16 rows, 4 accumulators)
    float4 a0 = p[0*DIM4], a1 = p[1*DIM4], a2 = p[2*DIM4], a3 = p[3*DIM4];
    #pragma unroll
    for (int i = 4; i < CHUNK; i += 4) {
        a0 = f4add(a0, p[(i+0)*DIM4]);
        a1 = f4add(a1, p[(i+1)*DIM4]);
        a2 = f4add(a2, p[(i+2)*DIM4]);
        a3 = f4add(a3, p[(i+3)*DIM4]);
    }
    float4 agg = f4add(f4add(a0, a1), f4add(a2, a3));

    float4* aggr_me = (float4*)(g_aggr + (size_t)bc * DIM);
    float4* incl_me = (float4*)(g_incl + (size_t)bc * DIM);

    __shared__ int sf;

    if (c == 0) {
        incl_me[t] = agg;
        __threadfence();
        __syncthreads();
        if (t == 0) st_rel(&g_flag[bc], 2);
    } else {
        aggr_me[t] = agg;
        __threadfence();
        __syncthreads();
        if (t == 0) st_rel(&g_flag[bc], 1);
    }

    // lookback: accumulate exclusive prefix 'run'
    float4 run = make_float4(0.f, 0.f, 0.f, 0.f);
    if (c > 0) {
        int j = bc - 1;
        while (true) {
            if (t == 0) {
                int f;
                do { f = ld_acq(&g_flag[j]); } while (f == 0);
                sf = f;
            }
            __syncthreads();
            const int f = sf;
            __syncthreads();
            const float4* src = (const float4*)((f == 2 ? g_incl : g_aggr) + (size_t)j * DIM);
            run = f4add(run, src[t]);
            if (f == 2) break;
            j--;
        }
        // publish inclusive prefix
        incl_me[t] = f4add(run, agg);
        __threadfence();
        __syncthreads();
        if (t == 0) st_rel(&g_flag[bc], 2);
    }

    // write cs rows (x rows re-read; hot in L1)
    float4* q = (float4*)(g_cs + ((size_t)b * (SLEN + 1) + (size_t)c * CHUNK) * DIM) + t;
    float4 r = run;
    #pragma unroll
    for (int i = 0; i < CHUNK; i += 4) {
        float4 v0 = p[(i+0)*DIM4], v1 = p[(i+1)*DIM4], v2 = p[(i+2)*DIM4], v3 = p[(i+3)*DIM4];
        q[(i+0)*DIM4] = r; r = f4add(r, v0);
        q[(i+1)*DIM4] = r; r = f4add(r, v1);
        q[(i+2)*DIM4] = r; r = f4add(r, v2);
        q[(i+3)*DIM4] = r; r = f4add(r, v3);
    }
    if (c == NCHUNK - 1) q[CHUNK * DIM4] = r;   // cs[SLEN]
}

// ---------------------------------------------------------------------------
// Kernel 2: span rows, 2 rows per block.  grid = NROWS/2, block = 192
// ---------------------------------------------------------------------------
__global__ __launch_bounds__(DIM4)
void span_kernel(const float* __restrict__ x,
                 const int* __restrict__ spans,
                 const int* __restrict__ pt_labels,
                 const float* __restrict__ wtab,
                 const float* __restrict__ ptab,
                 float* __restrict__ out) {
    const int t   = threadIdx.x;
    const int bn0 = blockIdx.x * 2;
    const int bn1 = bn0 + 1;
    const int b0 = bn0 >> 12, n0 = bn0 & (NSPAN - 1);
    const int b1 = bn1 >> 12, n1 = bn1 & (NSPAN - 1);

    const int i0a = spans[2*n0+0], i1a = spans[2*n0+1];
    const int i0b = spans[2*n1+0], i1b = spans[2*n1+1];
    const int wa = i1a - i0a + 1, wb = i1b - i0b + 1;

    const int bins[16] = {0,1,2,3,4,5,7,8,9,10,15,16,31,32,63,64};
    int ema = 0, emb = 0;
    #pragma unroll
    for (int i = 1; i < 16; i++) {
        ema = (wa >= bins[i]) ? i : ema;
        emb = (wb >= bins[i]) ? i : emb;
    }
    const int l0a = pt_labels[i0a], l1a = pt_labels[i1a];
    const int l0b = pt_labels[i0b], l1b = pt_labels[i1b];
    const float iwa = 1.0f / (float)wa, iwb = 1.0f / (float)wb;

    // issue all 8 big gather loads before any store
    const float4 csa0 = ((const float4*)(g_cs + ((size_t)b0*(SLEN+1) + i0a    )*DIM))[t];
    const float4 csa1 = ((const float4*)(g_cs + ((size_t)b0*(SLEN+1) + i1a + 1)*DIM))[t];
    const float4 xa0  = ((const float4*)(x    + ((size_t)b0*SLEN + i0a)*DIM))[t];
    const float4 xa1  = ((const float4*)(x    + ((size_t)b0*SLEN + i1a)*DIM))[t];
    const float4 csb0 = ((const float4*)(g_cs + ((size_t)b1*(SLEN+1) + i0b    )*DIM))[t];
    const float4 csb1 = ((const float4*)(g_cs + ((size_t)b1*(SLEN+1) + i1b + 1)*DIM))[t];
    const float4 xb0  = ((const float4*)(x    + ((size_t)b1*SLEN + i0b)*DIM))[t];
    const float4 xb1  = ((const float4*)(x    + ((size_t)b1*SLEN + i1b)*DIM))[t];

    float* ra = out + (size_t)bn0 * OUTW;
    float* rb = out + (size_t)bn1 * OUTW;

    float4 ma, mb;
    ma.x = (csa1.x - csa0.x) * iwa; ma.y = (csa1.y - csa0.y) * iwa;
    ma.z = (csa1.z - csa0.z) * iwa; ma.w = (csa1.w - csa0.w) * iwa;
    mb.x = (csb1.x - csb0.x) * iwb; mb.y = (csb1.y - csb0.y) * iwb;
    mb.z = (csb1.z - csb0.z) * iwb; mb.w = (csb1.w - csb0.w) * iwb;

    ((float4*)(ra + OFF_MEAN))[t] = ma;
    ((float4*)(ra + OFF_XS0 ))[t] = xa0;
    ((float4*)(ra + OFF_XS1 ))[t] = xa1;
    ((float4*)(rb + OFF_MEAN))[t] = mb;
    ((float4*)(rb + OFF_XS0 ))[t] = xb0;
    ((float4*)(rb + OFF_XS1 ))[t] = xb1;

    if (t < 5) {
        ((float4*)(ra + OFF_P0))[t] = ((const float4*)(ptab + l0a * 20))[t];
        ((float4*)(ra + OFF_P1))[t] = ((const float4*)(ptab + l1a * 20))[t];
        ((float4*)(ra + OFF_W ))[t] = ((const float4*)(wtab + ema * 20))[t];
        ((float4*)(rb + OFF_P0))[t] = ((const float4*)(ptab + l0b * 20))[t];
        ((float4*)(rb + OFF_P1))[t] = ((const float4*)(ptab + l1b * 20))[t];
        ((float4*)(rb + OFF_W ))[t] = ((const float4*)(wtab + emb * 20))[t];
    }
}

// ---------------------------------------------------------------------------
extern "C" void kernel_launch(void* const* d_in, const int* in_sizes, int n_in,
                              void* d_out, int out_size) {
    const float* x      = (const float*)d_in[0];
    const int*   spans  = (const int*)d_in[1];
    const int*   labels = (const int*)d_in[2];
    const float* wtab   = (const float*)d_in[3];
    const float* ptab   = (const float*)d_in[4];
    float*       out    = (float*)d_out;

    zero_flags_kernel<<<1, NCBLK>>>();
    scan_kernel      <<<NCBLK, DIM4>>>(x);
    span_kernel      <<<NROWS / 2, DIM4>>>(x, spans, labels, wtab, ptab, out);
}

// round 6
// speedup vs baseline: 1.3050x; 1.3050x over previous
#include <cuda_runtime.h>

// Fixed problem shapes (SpanRepresentation_32487132627590)
#define BATCH   4
#define SLEN    2048
#define DIM     768
#define DIM4    (DIM / 4)               // 192
#define NSPAN   4096
#define CHUNK   32
#define NCHUNK  (SLEN / CHUNK)          // 64
#define OUTW    2364
#define OFF_MEAN 0
#define OFF_XS0  768
#define OFF_P0   1536
#define OFF_XS1  1556
#define OFF_P1   2324
#define OFF_W    2344

// exclusive prefix sums cs[b, s, d], s in [0, SLEN]  (~25.2 MB)
__device__ float g_cs[(size_t)BATCH * (SLEN + 1) * DIM];
// per-chunk sums
__device__ float g_chunk[(size_t)BATCH * NCHUNK * DIM];

// ---------------------------------------------------------------------------
// Kernel 1: partial sums per (b, chunk, d).  grid = 256, block = 768
// ---------------------------------------------------------------------------
__global__ __launch_bounds__(DIM)
void chunksum_kernel(const float* __restrict__ x) {
    const int d  = threadIdx.x;            // 0..767
    const int bc = blockIdx.x;             // b*NCHUNK + c
    const float* p = x + (size_t)bc * CHUNK * DIM + d;

    float a0 = 0.f, a1 = 0.f, a2 = 0.f, a3 = 0.f;
    #pragma unroll
    for (int i = 0; i < CHUNK; i += 4) {
        a0 += p[(size_t)(i + 0) * DIM];
        a1 += p[(size_t)(i + 1) * DIM];
        a2 += p[(size_t)(i + 2) * DIM];
        a3 += p[(size_t)(i + 3) * DIM];
    }
    g_chunk[(size_t)bc * DIM + d] = (a0 + a1) + (a2 + a3);
}

// ---------------------------------------------------------------------------
// Kernel 2: in-chunk sequential scan -> cs.  grid = 256, block = 768
// ---------------------------------------------------------------------------
__global__ __launch_bounds__(DIM)
void scan_write_kernel(const float* __restrict__ x) {
    const int d  = threadIdx.x;
    const int bc = blockIdx.x;
    const int b  = bc / NCHUNK;
    const int c  = bc % NCHUNK;

    // exclusive prefix of chunk sums (L2-resident after kernel 1)
    float run = 0.f;
    const float* ch = g_chunk + (size_t)b * NCHUNK * DIM + d;
    for (int cc = 0; cc < c; cc++) run += ch[(size_t)cc * DIM];

    const float* p = x    + ((size_t)b * SLEN       + (size_t)c * CHUNK) * DIM + d;
    float*       q = g_cs + ((size_t)b * (SLEN + 1) + (size_t)c * CHUNK) * DIM + d;

    #pragma unroll 4
    for (int i = 0; i < CHUNK; i++) {
        q[(size_t)i * DIM] = run;           // cs[s] = exclusive prefix
        run += p[(size_t)i * DIM];
    }
    if (c == NCHUNK - 1) q[(size_t)CHUNK * DIM] = run;   // cs[SLEN]
}

// ---------------------------------------------------------------------------
// Kernel 3: one block per span n; loop over the 4 batches (spans are
// batch-shared, so indices/embeddings amortize 4x).  grid = 4096, block = 192
// ---------------------------------------------------------------------------
__global__ __launch_bounds__(DIM4)
void span_kernel(const float* __restrict__ x,
                 const int* __restrict__ spans,
                 const int* __restrict__ pt_labels,
                 const float* __restrict__ wtab,
                 const float* __restrict__ ptab,
                 float* __restrict__ out) {
    const int n = blockIdx.x;               // span index 0..4095
    const int t = threadIdx.x;              // 0..191

    const int i0 = spans[2 * n + 0];
    const int i1 = spans[2 * n + 1];
    const int width = i1 - i0 + 1;

    const int bins[16] = {0,1,2,3,4,5,7,8,9,10,15,16,31,32,63,64};
    int em = 0;
    #pragma unroll
    for (int i = 1; i < 16; i++) em = (width >= bins[i]) ? i : em;

    const int l0 = pt_labels[i0];
    const int l1 = pt_labels[i1];
    const float inv_w = 1.0f / (float)width;

    // small embedding segments (register-cached across batches)
    float4 e0, e1, ew;
    if (t < 5) {
        e0 = ((const float4*)(ptab + l0 * 20))[t];
        e1 = ((const float4*)(ptab + l1 * 20))[t];
        ew = ((const float4*)(wtab + em * 20))[t];
    }

    #pragma unroll
    for (int b = 0; b < BATCH; b++) {
        const float4 cs0 = ((const float4*)(g_cs + ((size_t)b * (SLEN + 1) + i0    ) * DIM))[t];
        const float4 cs1 = ((const float4*)(g_cs + ((size_t)b * (SLEN + 1) + i1 + 1) * DIM))[t];
        const float4 x0  = ((const float4*)(x    + ((size_t)b * SLEN + i0) * DIM))[t];
        const float4 x1  = ((const float4*)(x    + ((size_t)b * SLEN + i1) * DIM))[t];

        float4 m;
        m.x = (cs1.x - cs0.x) * inv_w;
        m.y = (cs1.y - cs0.y) * inv_w;
        m.z = (cs1.z - cs0.z) * inv_w;
        m.w = (cs1.w - cs0.w) * inv_w;

        float* orow = out + ((size_t)b * NSPAN + n) * OUTW;
        ((float4*)(orow + OFF_MEAN))[t] = m;
        ((float4*)(orow + OFF_XS0 ))[t] = x0;
        ((float4*)(orow + OFF_XS1 ))[t] = x1;
        if (t < 5) {
            ((float4*)(orow + OFF_P0))[t] = e0;
            ((float4*)(orow + OFF_P1))[t] = e1;
            ((float4*)(orow + OFF_W ))[t] = ew;
        }
    }
}

// ---------------------------------------------------------------------------
extern "C" void kernel_launch(void* const* d_in, const int* in_sizes, int n_in,
                              void* d_out, int out_size) {
    const float* x      = (const float*)d_in[0];
    const int*   spans  = (const int*)d_in[1];
    const int*   labels = (const int*)d_in[2];
    const float* wtab   = (const float*)d_in[3];
    const float* ptab   = (const float*)d_in[4];
    float*       out    = (float*)d_out;

    chunksum_kernel  <<<BATCH * NCHUNK, DIM>>>(x);
    scan_write_kernel<<<BATCH * NCHUNK, DIM>>>(x);
    span_kernel      <<<NSPAN, DIM4>>>(x, spans, labels, wtab, ptab, out);
}